// round 1
// baseline (speedup 1.0000x reference)
#include <cuda_runtime.h>
#include <math.h>

#define HH 65
#define WW 65
#define HW 4225
#define NH 8
#define DK 512
#define RW 33
#define HRW 2145
#define DHID 4096

// ---------------- scratch (device globals; no allocation allowed) ----------------
__device__ float g_q[DHID];
__device__ float g_u[NH * DK];
__device__ float g_qb[NH];
__device__ float g_A0[NH * HW];
__device__ float g_Wt1[DK * DK];
__device__ float g_Wt2[9 * DK * DK];
__device__ float g_F1[DK * HW];
__device__ float g_F2[DK * HW];
__device__ float g_F3[NH * HW];
__device__ float g_filt[2][NH * HRW];
__device__ float2 g_Fr[NH * HRW];
__device__ float2 g_Af[NH * HRW];
__device__ float2 g_Gr[NH * HRW];
__device__ float g_A[NH * HW];
__device__ float g_P[NH * HW];
__device__ float g_m[NH * DK];
__device__ float g_x[DHID];

#define TWO_PI 6.28318530717958647692f

// ---------------- q = Wq @ Q + bq (warp per row) ----------------
__global__ void k_qproj(const float* __restrict__ Q, const float* __restrict__ Wq,
                        const float* __restrict__ bq) {
    int r = blockIdx.x * 8 + (threadIdx.x >> 5);
    int lane = threadIdx.x & 31;
    const float* wr = Wq + r * DK;
    float acc = 0.f;
    for (int c = lane; c < DK; c += 32) acc += wr[c] * Q[c];
    #pragma unroll
    for (int o = 16; o > 0; o >>= 1) acc += __shfl_down_sync(0xffffffffu, acc, o);
    if (lane == 0) g_q[r] = acc + bq[r];
}

// ---------------- u[h,c] = sum_d Wk[h*512+d, c] * q[h*512+d]; qb[h]=q_h·bk_h ----------------
__global__ void k_u(const float* __restrict__ Wk, const float* __restrict__ bk) {
    int h = blockIdx.x;
    int tid = threadIdx.x;  // 512
    __shared__ float qs[DK];
    __shared__ float red[DK];
    qs[tid] = g_q[h * DK + tid];
    __syncthreads();
    float acc = 0.f;
    const float* wb = Wk + h * DK * DK + tid;
    for (int d = 0; d < DK; d++) acc += wb[d * DK] * qs[d];
    g_u[h * DK + tid] = acc;
    red[tid] = qs[tid] * bk[h * DK + tid];
    __syncthreads();
    for (int st = 256; st > 0; st >>= 1) {
        if (tid < st) red[tid] += red[tid + st];
        __syncthreads();
    }
    if (tid == 0) g_qb[h] = red[0];
}

// ---------------- A0[h,s] = (u_h · K[:,s] + qb[h]) / sqrt(512) ----------------
__global__ void k_A0(const float* __restrict__ K) {
    __shared__ float us[NH * DK];
    __shared__ float qbs[NH];
    int tid = threadIdx.x;
    for (int i = tid; i < NH * DK; i += 256) us[i] = g_u[i];
    if (tid < NH) qbs[tid] = g_qb[tid];
    __syncthreads();
    int s = blockIdx.x * 256 + tid;
    if (s >= HW) return;
    float acc[NH] = {};
    for (int c = 0; c < DK; c++) {
        float kv = K[c * HW + s];
        #pragma unroll
        for (int h = 0; h < NH; h++) acc[h] += us[h * DK + c] * kv;
    }
    const float scale = 0.04419417382415922f;  // 1/sqrt(512)
    #pragma unroll
    for (int h = 0; h < NH; h++) g_A0[h * HW + s] = (acc[h] + qbs[h]) * scale;
}

// ---------------- weight transposes ----------------
__global__ void k_tr1(const float* __restrict__ Wsrc) {
    int idx = blockIdx.x * 256 + threadIdx.x;  // i*512+o
    int o = idx & 511, i = idx >> 9;
    g_Wt1[idx] = Wsrc[o * DK + i];
}
__global__ void k_tr2(const float* __restrict__ Wsrc) {
    int idx = blockIdx.x * 256 + threadIdx.x;  // (t*512+i)*512+o
    int o = idx & 511;
    int i = (idx >> 9) & 511;
    int t = idx >> 18;
    g_Wt2[idx] = Wsrc[(o * DK + i) * 9 + t];
}

// ---------------- 1x1 conv as GEMM: F1[o,s] = sum_i W[o,i]*K[i,s] ----------------
__global__ void __launch_bounds__(256) k_gemm1(const float* __restrict__ B) {
    __shared__ float As[16][64];
    __shared__ float Bs[16][64];
    int tid = threadIdx.x;
    int n0 = blockIdx.x * 64, m0 = blockIdx.y * 64;
    int tx = tid & 15, ty = tid >> 4;
    float acc[4][4] = {};
    for (int kc = 0; kc < DK; kc += 16) {
        #pragma unroll
        for (int i = 0; i < 4; i++) {
            int idx = tid + i * 256;
            int k = idx >> 6, mm = idx & 63;
            As[k][mm] = g_Wt1[(kc + k) * DK + m0 + mm];
            int n = n0 + mm;
            Bs[k][mm] = (n < HW) ? B[(kc + k) * HW + n] : 0.f;
        }
        __syncthreads();
        #pragma unroll
        for (int k = 0; k < 16; k++) {
            float4 a4 = *(const float4*)&As[k][ty * 4];
            float4 b4 = *(const float4*)&Bs[k][tx * 4];
            acc[0][0] += a4.x * b4.x; acc[0][1] += a4.x * b4.y; acc[0][2] += a4.x * b4.z; acc[0][3] += a4.x * b4.w;
            acc[1][0] += a4.y * b4.x; acc[1][1] += a4.y * b4.y; acc[1][2] += a4.y * b4.z; acc[1][3] += a4.y * b4.w;
            acc[2][0] += a4.z * b4.x; acc[2][1] += a4.z * b4.y; acc[2][2] += a4.z * b4.z; acc[2][3] += a4.z * b4.w;
            acc[3][0] += a4.w * b4.x; acc[3][1] += a4.w * b4.y; acc[3][2] += a4.w * b4.z; acc[3][3] += a4.w * b4.w;
        }
        __syncthreads();
    }
    #pragma unroll
    for (int im = 0; im < 4; im++) {
        int m = m0 + ty * 4 + im;
        #pragma unroll
        for (int in_ = 0; in_ < 4; in_++) {
            int n = n0 + tx * 4 + in_;
            if (n < HW) g_F1[m * HW + n] = acc[im][in_];
        }
    }
}

// ---------------- 3x3 conv: F2 = conv3x3(relu(F1), W2) + F1 ----------------
__global__ void __launch_bounds__(256) k_conv2() {
    __shared__ float As[16][64];
    __shared__ float Bs[16][64];
    int tid = threadIdx.x;
    int n0 = blockIdx.x * 64, m0 = blockIdx.y * 64;
    int tx = tid & 15, ty = tid >> 4;
    int ny[4], nx_[4];
    bool nin[4];
    #pragma unroll
    for (int i = 0; i < 4; i++) {
        int idx = tid + i * 256;
        int nn = idx & 63;
        int n = n0 + nn;
        nin[i] = (n < HW);
        int nc = nin[i] ? n : 0;
        ny[i] = nc / WW;
        nx_[i] = nc % WW;
    }
    float acc[4][4] = {};
    for (int t = 0; t < 9; t++) {
        int dy = t / 3 - 1, dx = t % 3 - 1;
        const float* wt = g_Wt2 + t * DK * DK;
        for (int kc = 0; kc < DK; kc += 16) {
            #pragma unroll
            for (int i = 0; i < 4; i++) {
                int idx = tid + i * 256;
                int k = idx >> 6, mm = idx & 63;
                As[k][mm] = wt[(kc + k) * DK + m0 + mm];
                int yy = ny[i] + dy, xx = nx_[i] + dx;
                float v = 0.f;
                if (nin[i] && yy >= 0 && yy < HH && xx >= 0 && xx < WW)
                    v = fmaxf(g_F1[(kc + k) * HW + yy * WW + xx], 0.f);
                Bs[k][mm] = v;
            }
            __syncthreads();
            #pragma unroll
            for (int k = 0; k < 16; k++) {
                float4 a4 = *(const float4*)&As[k][ty * 4];
                float4 b4 = *(const float4*)&Bs[k][tx * 4];
                acc[0][0] += a4.x * b4.x; acc[0][1] += a4.x * b4.y; acc[0][2] += a4.x * b4.z; acc[0][3] += a4.x * b4.w;
                acc[1][0] += a4.y * b4.x; acc[1][1] += a4.y * b4.y; acc[1][2] += a4.y * b4.z; acc[1][3] += a4.y * b4.w;
                acc[2][0] += a4.z * b4.x; acc[2][1] += a4.z * b4.y; acc[2][2] += a4.z * b4.z; acc[2][3] += a4.z * b4.w;
                acc[3][0] += a4.w * b4.x; acc[3][1] += a4.w * b4.y; acc[3][2] += a4.w * b4.z; acc[3][3] += a4.w * b4.w;
            }
            __syncthreads();
        }
    }
    #pragma unroll
    for (int im = 0; im < 4; im++) {
        int m = m0 + ty * 4 + im;
        #pragma unroll
        for (int in_ = 0; in_ < 4; in_++) {
            int n = n0 + tx * 4 + in_;
            if (n < HW) g_F2[m * HW + n] = acc[im][in_] + g_F1[m * HW + n];
        }
    }
}

// ---------------- F3[h,s] = relu(sum_i W3[h,i]*relu(F2[i,s])) ----------------
__global__ void k_f3(const float* __restrict__ W3) {
    __shared__ float ws[NH * DK];
    int tid = threadIdx.x;
    for (int i = tid; i < NH * DK; i += 256) ws[i] = W3[i];
    __syncthreads();
    int s = blockIdx.x * 256 + tid;
    if (s >= HW) return;
    float acc[NH] = {};
    for (int c = 0; c < DK; c++) {
        float v = fmaxf(g_F2[c * HW + s], 0.f);
        #pragma unroll
        for (int h = 0; h < NH; h++) acc[h] += ws[h * DK + c] * v;
    }
    #pragma unroll
    for (int h = 0; h < NH; h++) g_F3[h * HW + s] = fmaxf(acc[h], 0.f);
}

// ---------------- g[h,j] = sum_s Wd[j,s]*F3[h,s] + bd[j] (warp per j) ----------------
__global__ void k_down(const float* __restrict__ Wd, const float* __restrict__ bd, int br) {
    int warp = threadIdx.x >> 5, lane = threadIdx.x & 31;
    int j = blockIdx.x * 8 + warp;
    if (j >= HRW) return;
    const float* wr = Wd + j * HW;
    float acc[NH] = {};
    for (int s = lane; s < HW; s += 32) {
        float wv = wr[s];
        #pragma unroll
        for (int h = 0; h < NH; h++) acc[h] += wv * g_F3[h * HW + s];
    }
    #pragma unroll
    for (int h = 0; h < NH; h++) {
        #pragma unroll
        for (int o = 16; o > 0; o >>= 1) acc[h] += __shfl_down_sync(0xffffffffu, acc[h], o);
    }
    if (lane == 0) {
        float b = bd[j];
        #pragma unroll
        for (int h = 0; h < NH; h++) g_filt[br][h * HRW + j] = acc[h] + b;
    }
}

// ---------------- forward rFFT over rows ----------------
__global__ void k_fftrow() {
    int hy = blockIdx.x;
    int h = hy / HH, y = hy % HH;
    __shared__ float row[HH], twc[HH], tws[HH];
    int tid = threadIdx.x;  // 64
    for (int i = tid; i < HH; i += 64) {
        row[i] = g_A0[h * HW + y * WW + i];
        float sv, cv;
        sincosf(TWO_PI * (float)i / 65.f, &sv, &cv);
        twc[i] = cv; tws[i] = sv;
    }
    __syncthreads();
    if (tid < RW) {
        float re = 0.f, im = 0.f;
        for (int x = 0; x < HH; x++) {
            int t = (tid * x) % 65;
            re += row[x] * twc[t];
            im -= row[x] * tws[t];
        }
        g_Fr[h * HRW + y * RW + tid] = make_float2(re, im);
    }
}

// ---------------- forward FFT over cols + spectral modification ----------------
__global__ void k_fftcol_mod() {
    __shared__ float twc[HH], tws[HH];
    for (int i = threadIdx.x; i < HH; i += 256) {
        float sv, cv;
        sincosf(TWO_PI * (float)i / 65.f, &sv, &cv);
        twc[i] = cv; tws[i] = sv;
    }
    __syncthreads();
    int idx = blockIdx.x * 256 + threadIdx.x;
    if (idx >= NH * HRW) return;
    int h = idx / HRW, r = idx % HRW;
    int ky = r / RW, kx = r % RW;
    const float2* fr = g_Fr + h * HRW + kx;
    float re = 0.f, im = 0.f;
    for (int y = 0; y < HH; y++) {
        int t = (ky * y) % 65;
        float c = twc[t], s = tws[t];
        float2 f = fr[y * RW];
        re += f.x * c + f.y * s;
        im += f.y * c - f.x * s;
    }
    float mag = sqrtf(re * re + im * im);
    float ang = atan2f(im, re);
    float a = g_filt[0][idx] * mag;
    float p = g_filt[1][idx] * ang;
    float sp, cp;
    sincosf(p, &sp, &cp);
    g_Af[idx] = make_float2(a * cp, a * sp);
}

// ---------------- inverse FFT over cols (1/65) ----------------
__global__ void k_invcol() {
    __shared__ float twc[HH], tws[HH];
    for (int i = threadIdx.x; i < HH; i += 256) {
        float sv, cv;
        sincosf(TWO_PI * (float)i / 65.f, &sv, &cv);
        twc[i] = cv; tws[i] = sv;
    }
    __syncthreads();
    int idx = blockIdx.x * 256 + threadIdx.x;
    if (idx >= NH * HRW) return;
    int h = idx / HRW, r = idx % HRW;
    int y = r / RW, kx = r % RW;
    const float2* af = g_Af + h * HRW + kx;
    float re = 0.f, im = 0.f;
    for (int ky = 0; ky < HH; ky++) {
        int t = (ky * y) % 65;
        float c = twc[t], s = tws[t];
        float2 f = af[ky * RW];
        re += f.x * c - f.y * s;
        im += f.y * c + f.x * s;
    }
    g_Gr[idx] = make_float2(re * (1.f / 65.f), im * (1.f / 65.f));
}

// ---------------- inverse rFFT over rows (1/65) ----------------
__global__ void k_invrow() {
    __shared__ float twc[HH], tws[HH];
    for (int i = threadIdx.x; i < HH; i += 256) {
        float sv, cv;
        sincosf(TWO_PI * (float)i / 65.f, &sv, &cv);
        twc[i] = cv; tws[i] = sv;
    }
    __syncthreads();
    int idx = blockIdx.x * 256 + threadIdx.x;
    if (idx >= NH * HW) return;
    int h = idx / HW, s = idx % HW;
    int y = s / WW, x = s % WW;
    const float2* gp = g_Gr + h * HRW + y * RW;
    float acc = gp[0].x;
    for (int k = 1; k < RW; k++) {
        int t = (k * x) % 65;
        acc += 2.f * (gp[k].x * twc[t] - gp[k].y * tws[t]);
    }
    g_A[idx] = acc * (1.f / 65.f);
}

// ---------------- softmax per head ----------------
__global__ void k_softmax() {
    int h = blockIdx.x, tid = threadIdx.x;
    __shared__ float red[256];
    const float* a = g_A + h * HW;
    float* p = g_P + h * HW;
    float mx = -3.4e38f;
    for (int s = tid; s < HW; s += 256) mx = fmaxf(mx, a[s]);
    red[tid] = mx;
    __syncthreads();
    for (int st = 128; st > 0; st >>= 1) {
        if (tid < st) red[tid] = fmaxf(red[tid], red[tid + st]);
        __syncthreads();
    }
    mx = red[0];
    __syncthreads();
    float sum = 0.f;
    for (int s = tid; s < HW; s += 256) {
        float e = expf(a[s] - mx);
        p[s] = e;
        sum += e;
    }
    red[tid] = sum;
    __syncthreads();
    for (int st = 128; st > 0; st >>= 1) {
        if (tid < st) red[tid] += red[tid + st];
        __syncthreads();
    }
    float inv = 1.f / red[0];
    for (int s = tid; s < HW; s += 256) p[s] *= inv;
}

// ---------------- m[h,c] = sum_s P[h,s]*K[c,s] (warp per c) ----------------
__global__ void k_m(const float* __restrict__ K) {
    int c = blockIdx.x * 8 + (threadIdx.x >> 5);
    int lane = threadIdx.x & 31;
    const float* kr = K + c * HW;
    float acc[NH] = {};
    for (int s = lane; s < HW; s += 32) {
        float kv = kr[s];
        #pragma unroll
        for (int h = 0; h < NH; h++) acc[h] += kv * g_P[h * HW + s];
    }
    #pragma unroll
    for (int h = 0; h < NH; h++) {
        #pragma unroll
        for (int o = 16; o > 0; o >>= 1) acc[h] += __shfl_down_sync(0xffffffffu, acc[h], o);
    }
    if (lane == 0) {
        #pragma unroll
        for (int h = 0; h < NH; h++) g_m[h * DK + c] = acc[h];
    }
}

// ---------------- x[r] = Wv[r,:]·m_h + bv[r] ----------------
__global__ void k_vproj(const float* __restrict__ Wv, const float* __restrict__ bv) {
    int r = blockIdx.x * 8 + (threadIdx.x >> 5);
    int lane = threadIdx.x & 31;
    int h = r >> 9;
    const float* mr = g_m + (h << 9);
    const float* wr = Wv + r * DK;
    float acc = 0.f;
    for (int c = lane; c < DK; c += 32) acc += wr[c] * mr[c];
    #pragma unroll
    for (int o = 16; o > 0; o >>= 1) acc += __shfl_down_sync(0xffffffffu, acc, o);
    if (lane == 0) g_x[r] = acc + bv[r];
}

// ---------------- out[r] = Wo[r,:]·x + bo[r] ----------------
__global__ void k_out(const float* __restrict__ Wo, const float* __restrict__ bo,
                      float* __restrict__ out) {
    int r = blockIdx.x * 8 + (threadIdx.x >> 5);
    int lane = threadIdx.x & 31;
    const float* wr = Wo + r * DHID;
    float acc = 0.f;
    for (int j = lane; j < DHID; j += 32) acc += wr[j] * g_x[j];
    #pragma unroll
    for (int o = 16; o > 0; o >>= 1) acc += __shfl_down_sync(0xffffffffu, acc, o);
    if (lane == 0) out[r] = acc + bo[r];
}

extern "C" void kernel_launch(void* const* d_in, const int* in_sizes, int n_in,
                              void* d_out, int out_size) {
    const float* Q    = (const float*)d_in[0];
    const float* K    = (const float*)d_in[1];
    const float* Wq   = (const float*)d_in[2];
    const float* bq   = (const float*)d_in[3];
    const float* Wk   = (const float*)d_in[4];
    const float* bk   = (const float*)d_in[5];
    const float* Wv   = (const float*)d_in[6];
    const float* bv   = (const float*)d_in[7];
    const float* Wo   = (const float*)d_in[8];
    const float* bo   = (const float*)d_in[9];
    const float* amp1 = (const float*)d_in[10];
    const float* amp2 = (const float*)d_in[11];
    const float* amp3 = (const float*)d_in[12];
    const float* pha1 = (const float*)d_in[13];
    const float* pha2 = (const float*)d_in[14];
    const float* pha3 = (const float*)d_in[15];
    const float* Wd1  = (const float*)d_in[16];
    const float* bd1  = (const float*)d_in[17];
    const float* Wd2  = (const float*)d_in[18];
    const float* bd2  = (const float*)d_in[19];
    float* out = (float*)d_out;

    // attention-score path (collapsed projections)
    k_qproj<<<512, 256>>>(Q, Wq, bq);
    k_u<<<8, 512>>>(Wk, bk);
    k_A0<<<17, 256>>>(K);

    // two filter branches (amp = 0, pha = 1)
    for (int br = 0; br < 2; br++) {
        const float* w1 = br ? pha1 : amp1;
        const float* w2 = br ? pha2 : amp2;
        const float* w3 = br ? pha3 : amp3;
        const float* wd = br ? Wd2 : Wd1;
        const float* bd = br ? bd2 : bd1;
        k_tr1<<<1024, 256>>>(w1);
        k_tr2<<<9216, 256>>>(w2);
        k_gemm1<<<dim3(67, 8), 256>>>(K);
        k_conv2<<<dim3(67, 8), 256>>>();
        k_f3<<<17, 256>>>(w3);
        k_down<<<269, 256>>>(wd, bd, br);
    }

    // spectral filtering
    k_fftrow<<<NH * HH, 64>>>();
    k_fftcol_mod<<<68, 256>>>();
    k_invcol<<<68, 256>>>();
    k_invrow<<<133, 256>>>();
    k_softmax<<<NH, 256>>>();

    // output path
    k_m<<<64, 256>>>(K);
    k_vproj<<<512, 256>>>(Wv, bv);
    k_out<<<64, 256>>>(Wo, bo, out);
}

// round 7
// speedup vs baseline: 2.5176x; 2.5176x over previous
#include <cuda_runtime.h>
#include <math.h>
#include <stdint.h>

#define HH 65
#define WW 65
#define HW 4225
#define NH 8
#define DK 512
#define RW 33
#define HRW 2145
#define DHID 4096

// ---------------- scratch (device globals) ----------------
__device__ float g_q[DHID];
__device__ float g_up[8 * 4096];        // u partials over d-chunks
__device__ float g_qb[NH];
__device__ float g_A0p[4 * NH * HW];    // A0 partials over c-chunks
__device__ float g_A0[NH * HW];
__device__ float g_Wt1[DK * 1024];      // [k][br*512+o]
__device__ float g_Wt2[2 * 9 * DK * DK]; // [br*9+t][i][o]
__device__ float g_F1[2 * DK * HW];
__device__ float g_F2[2 * DK * HW];
__device__ float g_F3p[2 * 4 * NH * HW];
__device__ float g_F3[2 * NH * HW];
__device__ float g_filt[2][NH * HRW];
__device__ float2 g_Fr[NH * HRW];
__device__ float2 g_Af[NH * HRW];
__device__ float2 g_Gr[NH * HRW];
__device__ float g_A[NH * HW];
__device__ float g_P[NH * HW];
__device__ float g_m[NH * DK];
__device__ float g_x[DHID];

#define TWO_PI 6.28318530717958647692f

__device__ __forceinline__ uint32_t f2tf32(float f) {
    uint32_t u;
    asm("cvt.rna.tf32.f32 %0, %1;" : "=r"(u) : "f"(f));
    return u;
}

__device__ __forceinline__ void mma_tf32(
    float& c0, float& c1, float& c2, float& c3,
    uint32_t a0, uint32_t a1, uint32_t a2, uint32_t a3,
    uint32_t b0, uint32_t b1) {
    asm volatile(
        "mma.sync.aligned.m16n8k8.row.col.f32.tf32.tf32.f32 "
        "{%0,%1,%2,%3},{%4,%5,%6,%7},{%8,%9},{%0,%1,%2,%3};"
        : "+f"(c0), "+f"(c1), "+f"(c2), "+f"(c3)
        : "r"(a0), "r"(a1), "r"(a2), "r"(a3), "r"(b0), "r"(b1));
}

// ---------------- q = Wq @ Q + bq ----------------
__global__ void k_qproj(const float* __restrict__ Q, const float* __restrict__ Wq,
                        const float* __restrict__ bq) {
    int r = blockIdx.x * 8 + (threadIdx.x >> 5);
    int lane = threadIdx.x & 31;
    const float* wr = Wq + r * DK;
    float acc = 0.f;
    for (int c = lane; c < DK; c += 32) acc += wr[c] * Q[c];
    #pragma unroll
    for (int o = 16; o > 0; o >>= 1) acc += __shfl_down_sync(0xffffffffu, acc, o);
    if (lane == 0) g_q[r] = acc + bq[r];
}

// ---------------- qb[h] = q_h . bk_h (one block, warp per head) ----------------
__global__ void k_qb(const float* __restrict__ bk) {
    int h = threadIdx.x >> 5, lane = threadIdx.x & 31;
    float acc = 0.f;
    for (int d = lane; d < DK; d += 32) acc += g_q[h * DK + d] * bk[h * DK + d];
    #pragma unroll
    for (int o = 16; o > 0; o >>= 1) acc += __shfl_down_sync(0xffffffffu, acc, o);
    if (lane == 0) g_qb[h] = acc;
}

// ---------------- u partials ----------------
__global__ void k_u(const float* __restrict__ Wk) {
    int h = blockIdx.x, p = blockIdx.y;
    int tid = threadIdx.x;  // 512
    __shared__ float qs[64];
    if (tid < 64) qs[tid] = g_q[h * DK + p * 64 + tid];
    __syncthreads();
    float acc = 0.f;
    const float* wb = Wk + h * DK * DK + (p * 64) * DK + tid;
    #pragma unroll 8
    for (int d = 0; d < 64; d++) acc += wb[d * DK] * qs[d];
    g_up[p * 4096 + h * DK + tid] = acc;
}

// ---------------- A0 partials over c-chunks of 128 ----------------
__global__ void k_A0p(const float* __restrict__ K) {
    __shared__ float us[NH * 128];
    int tid = threadIdx.x;
    int c0 = blockIdx.y * 128;
    for (int i = tid; i < NH * 128; i += 256) {
        int h = i >> 7, c = i & 127;
        float s = 0.f;
        #pragma unroll
        for (int p = 0; p < 8; p++) s += g_up[p * 4096 + h * DK + c0 + c];
        us[i] = s;
    }
    __syncthreads();
    int s = blockIdx.x * 256 + tid;
    if (s >= HW) return;
    float acc[NH] = {};
    for (int c = 0; c < 128; c++) {
        float kv = K[(c0 + c) * HW + s];
        #pragma unroll
        for (int h = 0; h < NH; h++) acc[h] += us[h * 128 + c] * kv;
    }
    #pragma unroll
    for (int h = 0; h < NH; h++) g_A0p[blockIdx.y * NH * HW + h * HW + s] = acc[h];
}

__global__ void k_A0red() {
    int idx = blockIdx.x * 256 + threadIdx.x;
    if (idx >= NH * HW) return;
    int h = idx / HW;
    float s = g_A0p[idx] + g_A0p[NH * HW + idx] + g_A0p[2 * NH * HW + idx] + g_A0p[3 * NH * HW + idx];
    g_A0[idx] = (s + g_qb[h]) * 0.04419417382415922f;
}

// ---------------- tiled weight transposes ----------------
__global__ void k_tr1(const float* __restrict__ amp1, const float* __restrict__ pha1) {
    __shared__ float tile[32][33];
    int br = blockIdx.z;
    const float* src = br ? pha1 : amp1;
    int o0 = blockIdx.x * 32, i0 = blockIdx.y * 32;
    int tx = threadIdx.x, ty = threadIdx.y;
    #pragma unroll
    for (int r = 0; r < 32; r += 8)
        tile[ty + r][tx] = src[(o0 + ty + r) * DK + i0 + tx];
    __syncthreads();
    #pragma unroll
    for (int r = 0; r < 32; r += 8)
        g_Wt1[(i0 + ty + r) * 1024 + br * DK + o0 + tx] = tile[tx][ty + r];
}

__global__ void k_tr2(const float* __restrict__ amp2, const float* __restrict__ pha2) {
    __shared__ float tile[32][33];
    int bt = blockIdx.x;           // br*9 + t
    int br = bt / 9, t = bt % 9;
    const float* src = br ? pha2 : amp2;
    int o0 = blockIdx.y * 32, i0 = blockIdx.z * 32;
    int tx = threadIdx.x, ty = threadIdx.y;
    #pragma unroll
    for (int r = 0; r < 32; r += 8)
        tile[ty + r][tx] = src[((o0 + ty + r) * DK + i0 + tx) * 9 + t];
    __syncthreads();
    #pragma unroll
    for (int r = 0; r < 32; r += 8)
        g_Wt2[((size_t)bt * DK + i0 + ty + r) * DK + o0 + tx] = tile[tx][ty + r];
}

// ---------------- tf32 tensor-core GEMM / implicit conv ----------------
// Zero arrays anywhere: all fragments and accumulators are named scalars via macros.
// MODE 0: W=g_Wt1 (Mstride 1024), X=Kin, Y=g_F1, 1 tap, no relu/resid.
// MODE 1: W=g_Wt2[z], X=R=g_F1[z], Y=g_F2[z], 9 taps, relu-in, residual.

#define DECL_ACC(M,N) float c##M##N##x = 0.f, c##M##N##y = 0.f, c##M##N##z = 0.f, c##M##N##w = 0.f

#define LOADA(M) uint32_t a##M##0 = As[r0][wm + M*16 + g], a##M##1 = As[r0][wm + M*16 + g + 8], \
                          a##M##2 = As[r1][wm + M*16 + g], a##M##3 = As[r1][wm + M*16 + g + 8]
#define LOADB(N) uint32_t b##N##0 = Bs[r0][wn + N*8 + g], b##N##1 = Bs[r1][wn + N*8 + g]

#define DOMMA(M,N) mma_tf32(c##M##N##x, c##M##N##y, c##M##N##z, c##M##N##w, \
                            a##M##0, a##M##1, a##M##2, a##M##3, b##N##0, b##N##1)

#define EPI(M,N) do { \
    int mrow = m0 + wm + M*16 + g; \
    int nc = n0 + wn + N*8 + tg*2; \
    if (nc < HW) { \
        Yb[(size_t)mrow * HW + nc]       = c##M##N##x + (RESID ? Rb[(size_t)mrow * HW + nc] : 0.f); \
        Yb[(size_t)(mrow + 8) * HW + nc] = c##M##N##z + (RESID ? Rb[(size_t)(mrow + 8) * HW + nc] : 0.f); \
        if (nc + 1 < HW) { \
            Yb[(size_t)mrow * HW + nc + 1]       = c##M##N##y + (RESID ? Rb[(size_t)mrow * HW + nc + 1] : 0.f); \
            Yb[(size_t)(mrow + 8) * HW + nc + 1] = c##M##N##w + (RESID ? Rb[(size_t)(mrow + 8) * HW + nc + 1] : 0.f); \
        } \
    } \
} while (0)

template <int TAPS, bool RELU_IN, bool RESID, int MODE>
__global__ void __launch_bounds__(256) k_mma(const float* __restrict__ Kin) {
    __shared__ uint32_t As[16][136];
    __shared__ uint32_t Bs[16][136];
    int tid = threadIdx.x;
    int n0 = blockIdx.x * 128, m0 = blockIdx.y * 128;
    int z = blockIdx.z;

    const float* Wb;
    const float* Xb;
    const float* Rb;
    float* Yb;
    int Mstride;
    if (MODE == 0) {
        Wb = g_Wt1; Xb = Kin; Rb = g_F1; Yb = g_F1; Mstride = 1024;
    } else {
        Wb = g_Wt2 + (size_t)z * 9 * DK * DK;
        Xb = g_F1 + (size_t)z * DK * HW;
        Rb = g_F1 + (size_t)z * DK * HW;
        Yb = g_F2 + (size_t)z * DK * HW;
        Mstride = 512;
    }

    int col = tid & 127;
    int krow0 = tid >> 7;         // 0 or 1
    int n = n0 + col;
    bool nvalid = n < HW;
    int ny = n / WW, nx = n - ny * WW;

    int warp = tid >> 5, lane = tid & 31;
    int wm = (warp & 1) * 64, wn = (warp >> 1) * 32;
    int g = lane >> 2, tg = lane & 3;

    DECL_ACC(0,0); DECL_ACC(0,1); DECL_ACC(0,2); DECL_ACC(0,3);
    DECL_ACC(1,0); DECL_ACC(1,1); DECL_ACC(1,2); DECL_ACC(1,3);
    DECL_ACC(2,0); DECL_ACC(2,1); DECL_ACC(2,2); DECL_ACC(2,3);
    DECL_ACC(3,0); DECL_ACC(3,1); DECL_ACC(3,2); DECL_ACC(3,3);

    for (int t = 0; t < TAPS; t++) {
        int dy = (TAPS == 1) ? 0 : (t / 3 - 1);
        int dx = (TAPS == 1) ? 0 : (t % 3 - 1);
        int yy = ny + dy, xx = nx + dx;
        bool ok = nvalid && (unsigned)yy < HH && (unsigned)xx < WW;
        int src = ok ? (yy * WW + xx) : 0;
        const float* wrow = Wb + (size_t)(t * DK) * Mstride + m0 + col;
        for (int kc = 0; kc < DK; kc += 16) {
            #pragma unroll
            for (int i = 0; i < 8; i++) {
                int kr = i * 2 + krow0;
                As[kr][col] = f2tf32(wrow[(size_t)(kc + kr) * Mstride]);
                float v = 0.f;
                if (ok) {
                    v = Xb[(kc + kr) * HW + src];
                    if (RELU_IN) v = fmaxf(v, 0.f);
                }
                Bs[kr][col] = f2tf32(v);
            }
            __syncthreads();
            #pragma unroll
            for (int kf = 0; kf < 2; kf++) {
                int r0 = kf * 8 + tg, r1 = kf * 8 + tg + 4;
                LOADA(0); LOADA(1); LOADA(2); LOADA(3);
                LOADB(0); LOADB(1); LOADB(2); LOADB(3);
                DOMMA(0,0); DOMMA(0,1); DOMMA(0,2); DOMMA(0,3);
                DOMMA(1,0); DOMMA(1,1); DOMMA(1,2); DOMMA(1,3);
                DOMMA(2,0); DOMMA(2,1); DOMMA(2,2); DOMMA(2,3);
                DOMMA(3,0); DOMMA(3,1); DOMMA(3,2); DOMMA(3,3);
            }
            __syncthreads();
        }
    }
    EPI(0,0); EPI(0,1); EPI(0,2); EPI(0,3);
    EPI(1,0); EPI(1,1); EPI(1,2); EPI(1,3);
    EPI(2,0); EPI(2,1); EPI(2,2); EPI(2,3);
    EPI(3,0); EPI(3,1); EPI(3,2); EPI(3,3);
}

// ---------------- F3 partials: sum_{c in chunk} W3[h,c]*relu(F2[c,s]) ----------------
__global__ void k_f3p(const float* __restrict__ amp3, const float* __restrict__ pha3) {
    __shared__ float ws[NH * 128];
    int tid = threadIdx.x;
    int c0 = blockIdx.y * 128;
    int br = blockIdx.z;
    const float* W3 = br ? pha3 : amp3;
    const float* F2b = g_F2 + (size_t)br * DK * HW;
    for (int i = tid; i < NH * 128; i += 256) {
        int h = i >> 7, c = i & 127;
        ws[i] = W3[h * DK + c0 + c];
    }
    __syncthreads();
    int s = blockIdx.x * 256 + tid;
    if (s >= HW) return;
    float acc[NH] = {};
    for (int c = 0; c < 128; c++) {
        float v = fmaxf(F2b[(c0 + c) * HW + s], 0.f);
        #pragma unroll
        for (int h = 0; h < NH; h++) acc[h] += ws[h * 128 + c] * v;
    }
    #pragma unroll
    for (int h = 0; h < NH; h++)
        g_F3p[((size_t)br * 4 + blockIdx.y) * NH * HW + h * HW + s] = acc[h];
}

__global__ void k_f3red() {
    int idx = blockIdx.x * 256 + threadIdx.x;
    if (idx >= NH * HW) return;
    int br = blockIdx.y;
    const float* p = g_F3p + (size_t)br * 4 * NH * HW;
    float s = p[idx] + p[NH * HW + idx] + p[2 * NH * HW + idx] + p[3 * NH * HW + idx];
    g_F3[br * NH * HW + idx] = fmaxf(s, 0.f);
}

// ---------------- down-proj (warp per output j) ----------------
__global__ void k_down(const float* __restrict__ Wd1, const float* __restrict__ bd1,
                       const float* __restrict__ Wd2, const float* __restrict__ bd2) {
    int warp = threadIdx.x >> 5, lane = threadIdx.x & 31;
    int j = blockIdx.x * 8 + warp;
    int br = blockIdx.y;
    if (j >= HRW) return;
    const float* Wd = br ? Wd2 : Wd1;
    const float* bd = br ? bd2 : bd1;
    const float* F3b = g_F3 + br * NH * HW;
    const float* wr = Wd + (size_t)j * HW;
    float acc[NH] = {};
    for (int s = lane; s < HW; s += 32) {
        float wv = wr[s];
        #pragma unroll
        for (int h = 0; h < NH; h++) acc[h] += wv * F3b[h * HW + s];
    }
    #pragma unroll
    for (int h = 0; h < NH; h++) {
        #pragma unroll
        for (int o = 16; o > 0; o >>= 1) acc[h] += __shfl_down_sync(0xffffffffu, acc[h], o);
    }
    if (lane == 0) {
        float b = bd[j];
        #pragma unroll
        for (int h = 0; h < NH; h++) g_filt[br][h * HRW + j] = acc[h] + b;
    }
}

// ---------------- FFT chain ----------------
__global__ void k_fftrow() {
    int hy = blockIdx.x;
    int h = hy / HH, y = hy % HH;
    __shared__ float row[HH], twc[HH], tws[HH];
    int tid = threadIdx.x;  // 64
    for (int i = tid; i < HH; i += 64) {
        row[i] = g_A0[h * HW + y * WW + i];
        float sv, cv;
        sincosf(TWO_PI * (float)i / 65.f, &sv, &cv);
        twc[i] = cv; tws[i] = sv;
    }
    __syncthreads();
    if (tid < RW) {
        float re = 0.f, im = 0.f;
        for (int x = 0; x < HH; x++) {
            int t = (tid * x) % 65;
            re += row[x] * twc[t];
            im -= row[x] * tws[t];
        }
        g_Fr[h * HRW + y * RW + tid] = make_float2(re, im);
    }
}

__global__ void k_fftcol_mod() {
    __shared__ float twc[HH], tws[HH];
    for (int i = threadIdx.x; i < HH; i += 256) {
        float sv, cv;
        sincosf(TWO_PI * (float)i / 65.f, &sv, &cv);
        twc[i] = cv; tws[i] = sv;
    }
    __syncthreads();
    int idx = blockIdx.x * 256 + threadIdx.x;
    if (idx >= NH * HRW) return;
    int h = idx / HRW, r = idx % HRW;
    int ky = r / RW, kx = r % RW;
    const float2* fr = g_Fr + h * HRW + kx;
    float re = 0.f, im = 0.f;
    for (int y = 0; y < HH; y++) {
        int t = (ky * y) % 65;
        float c = twc[t], s = tws[t];
        float2 f = fr[y * RW];
        re += f.x * c + f.y * s;
        im += f.y * c - f.x * s;
    }
    float mag = sqrtf(re * re + im * im);
    float ang = atan2f(im, re);
    float a = g_filt[0][idx] * mag;
    float p = g_filt[1][idx] * ang;
    float sp, cp;
    sincosf(p, &sp, &cp);
    g_Af[idx] = make_float2(a * cp, a * sp);
}

__global__ void k_invcol() {
    __shared__ float twc[HH], tws[HH];
    for (int i = threadIdx.x; i < HH; i += 256) {
        float sv, cv;
        sincosf(TWO_PI * (float)i / 65.f, &sv, &cv);
        twc[i] = cv; tws[i] = sv;
    }
    __syncthreads();
    int idx = blockIdx.x * 256 + threadIdx.x;
    if (idx >= NH * HRW) return;
    int h = idx / HRW, r = idx % HRW;
    int y = r / RW, kx = r % RW;
    const float2* af = g_Af + h * HRW + kx;
    float re = 0.f, im = 0.f;
    for (int ky = 0; ky < HH; ky++) {
        int t = (ky * y) % 65;
        float c = twc[t], s = tws[t];
        float2 f = af[ky * RW];
        re += f.x * c - f.y * s;
        im += f.y * c + f.x * s;
    }
    g_Gr[idx] = make_float2(re * (1.f / 65.f), im * (1.f / 65.f));
}

__global__ void k_invrow() {
    __shared__ float twc[HH], tws[HH];
    for (int i = threadIdx.x; i < HH; i += 256) {
        float sv, cv;
        sincosf(TWO_PI * (float)i / 65.f, &sv, &cv);
        twc[i] = cv; tws[i] = sv;
    }
    __syncthreads();
    int idx = blockIdx.x * 256 + threadIdx.x;
    if (idx >= NH * HW) return;
    int h = idx / HW, s = idx % HW;
    int y = s / WW, x = s % WW;
    const float2* gp = g_Gr + h * HRW + y * RW;
    float acc = gp[0].x;
    for (int k = 1; k < RW; k++) {
        int t = (k * x) % 65;
        acc += 2.f * (gp[k].x * twc[t] - gp[k].y * tws[t]);
    }
    g_A[idx] = acc * (1.f / 65.f);
}

// ---------------- softmax per head ----------------
__global__ void k_softmax() {
    int h = blockIdx.x, tid = threadIdx.x;
    __shared__ float red[256];
    const float* a = g_A + h * HW;
    float* p = g_P + h * HW;
    float mx = -3.4e38f;
    for (int s = tid; s < HW; s += 256) mx = fmaxf(mx, a[s]);
    red[tid] = mx;
    __syncthreads();
    for (int st = 128; st > 0; st >>= 1) {
        if (tid < st) red[tid] = fmaxf(red[tid], red[tid + st]);
        __syncthreads();
    }
    mx = red[0];
    __syncthreads();
    float sum = 0.f;
    for (int s = tid; s < HW; s += 256) {
        float e = expf(a[s] - mx);
        p[s] = e;
        sum += e;
    }
    red[tid] = sum;
    __syncthreads();
    for (int st = 128; st > 0; st >>= 1) {
        if (tid < st) red[tid] += red[tid + st];
        __syncthreads();
    }
    float inv = 1.f / red[0];
    for (int s = tid; s < HW; s += 256) p[s] *= inv;
}

// ---------------- m[h,c] = sum_s P[h,s]*K[c,s] ----------------
__global__ void k_m(const float* __restrict__ K) {
    int c = blockIdx.x * 8 + (threadIdx.x >> 5);
    int lane = threadIdx.x & 31;
    const float* kr = K + c * HW;
    float acc[NH] = {};
    for (int s = lane; s < HW; s += 32) {
        float kv = kr[s];
        #pragma unroll
        for (int h = 0; h < NH; h++) acc[h] += kv * g_P[h * HW + s];
    }
    #pragma unroll
    for (int h = 0; h < NH; h++) {
        #pragma unroll
        for (int o = 16; o > 0; o >>= 1) acc[h] += __shfl_down_sync(0xffffffffu, acc[h], o);
    }
    if (lane == 0) {
        #pragma unroll
        for (int h = 0; h < NH; h++) g_m[h * DK + c] = acc[h];
    }
}

__global__ void k_vproj(const float* __restrict__ Wv, const float* __restrict__ bv) {
    int r = blockIdx.x * 8 + (threadIdx.x >> 5);
    int lane = threadIdx.x & 31;
    int h = r >> 9;
    const float* mr = g_m + (h << 9);
    const float* wr = Wv + r * DK;
    float acc = 0.f;
    for (int c = lane; c < DK; c += 32) acc += wr[c] * mr[c];
    #pragma unroll
    for (int o = 16; o > 0; o >>= 1) acc += __shfl_down_sync(0xffffffffu, acc, o);
    if (lane == 0) g_x[r] = acc + bv[r];
}

__global__ void k_out(const float* __restrict__ Wo, const float* __restrict__ bo,
                      float* __restrict__ out) {
    int r = blockIdx.x * 8 + (threadIdx.x >> 5);
    int lane = threadIdx.x & 31;
    const float* wr = Wo + r * DHID;
    float acc = 0.f;
    for (int j = lane; j < DHID; j += 32) acc += wr[j] * g_x[j];
    #pragma unroll
    for (int o = 16; o > 0; o >>= 1) acc += __shfl_down_sync(0xffffffffu, acc, o);
    if (lane == 0) out[r] = acc + bo[r];
}

extern "C" void kernel_launch(void* const* d_in, const int* in_sizes, int n_in,
                              void* d_out, int out_size) {
    const float* Q    = (const float*)d_in[0];
    const float* K    = (const float*)d_in[1];
    const float* Wq   = (const float*)d_in[2];
    const float* bq   = (const float*)d_in[3];
    const float* Wk   = (const float*)d_in[4];
    const float* bk   = (const float*)d_in[5];
    const float* Wv   = (const float*)d_in[6];
    const float* bv   = (const float*)d_in[7];
    const float* Wo   = (const float*)d_in[8];
    const float* bo   = (const float*)d_in[9];
    const float* amp1 = (const float*)d_in[10];
    const float* amp2 = (const float*)d_in[11];
    const float* amp3 = (const float*)d_in[12];
    const float* pha1 = (const float*)d_in[13];
    const float* pha2 = (const float*)d_in[14];
    const float* pha3 = (const float*)d_in[15];
    const float* Wd1  = (const float*)d_in[16];
    const float* bd1  = (const float*)d_in[17];
    const float* Wd2  = (const float*)d_in[18];
    const float* bd2  = (const float*)d_in[19];
    float* out = (float*)d_out;

    // attention-score path
    k_qproj<<<512, 256>>>(Q, Wq, bq);
    k_qb<<<1, 256>>>(bk);
    k_u<<<dim3(8, 8), 512>>>(Wk);
    k_A0p<<<dim3(17, 4), 256>>>(K);
    k_A0red<<<133, 256>>>();

    // weight reshuffles (both branches)
    k_tr1<<<dim3(16, 16, 2), dim3(32, 8)>>>(amp1, pha1);
    k_tr2<<<dim3(18, 16, 16), dim3(32, 8)>>>(amp2, pha2);

    // 1x1 conv, both branches batched as one M=1024 GEMM (MODE 0)
    k_mma<1, false, false, 0><<<dim3(34, 8, 1), 256>>>(K);

    // 3x3 conv + residual, branches via blockIdx.z (MODE 1)
    k_mma<9, true, true, 1><<<dim3(34, 4, 2), 256>>>(K);

    k_f3p<<<dim3(17, 4, 2), 256>>>(amp3, pha3);
    k_f3red<<<dim3(133, 2), 256>>>();
    k_down<<<dim3(269, 2), 256>>>(Wd1, bd1, Wd2, bd2);

    // spectral filtering
    k_fftrow<<<NH * HH, 64>>>();
    k_fftcol_mod<<<68, 256>>>();
    k_invcol<<<68, 256>>>();
    k_invrow<<<133, 256>>>();
    k_softmax<<<NH, 256>>>();

    // output path
    k_m<<<64, 256>>>(K);
    k_vproj<<<512, 256>>>(Wv, bv);
    k_out<<<64, 256>>>(Wo, bo, out);
}